// round 11
// baseline (speedup 1.0000x reference)
#include <cuda_runtime.h>
#include <cuda_bf16.h>
#include <cstdint>
#include <cstddef>

// Problem constants
#define B_   32
#define D_   512
#define P_   1024
#define N_   32768
#define K_   4096
#define TM   128           // rows per CTA
#define TK   64            // codes per k-tile
#define NKT  (K_/TK)       // 64 k-tiles
#define NBLK (N_/TM)       // 256 blocks
#define EPS  2.0f          // bf16 score error window (~7 sigma)

#define ASTRIDE 1040       // bytes per staged row (520 bf16): conflict-free ldmatrix

// Dynamic smem layout (bytes)
#define SM_EN    0                       // float[4096] exact ||e_k||^2
#define SM_KB    16384                   // int[128]
#define SM_LRED  16896                   // float[256]
#define SM_RING  18432                   // 3 stage buffers, 64 rows each
#define SM_BSZ   (TK * ASTRIDE)          // 66560
#define SM_TOTAL (SM_RING + 3 * SM_BSZ)  // 218112

__device__ float g_enorm[K_];
__device__ float g_losspart[NBLK];
__device__ __nv_bfloat16 g_Ebf[(size_t)K_ * D_];   // E bf16 row-major [k][d]
__device__ __nv_bfloat16 g_Zbf[(size_t)N_ * D_];   // z bf16 row-major [n][d]

// ---------------- PTX helpers (baseline ISA only) ----------------
__device__ __forceinline__ uint32_t smem_u32(const void* p) {
    uint32_t a;
    asm("{ .reg .u64 t; cvta.to.shared.u64 t, %1; cvt.u32.u64 %0, t; }"
        : "=r"(a) : "l"(p));
    return a;
}
__device__ __forceinline__ void cp_async16(uint32_t dst, const void* src) {
    asm volatile("cp.async.cg.shared.global [%0], [%1], 16;"
                 :: "r"(dst), "l"(src) : "memory");
}
__device__ __forceinline__ void cp_commit() {
    asm volatile("cp.async.commit_group;" ::: "memory");
}
__device__ __forceinline__ void cp_wait0() {
    asm volatile("cp.async.wait_group 0;" ::: "memory");
}
__device__ __forceinline__ void cp_wait1() {
    asm volatile("cp.async.wait_group 1;" ::: "memory");
}
__device__ __forceinline__ void ldsm_x4(uint32_t* r, uint32_t addr) {
    asm volatile("ldmatrix.sync.aligned.m8n8.x4.shared.b16 {%0,%1,%2,%3}, [%4];"
                 : "=r"(r[0]), "=r"(r[1]), "=r"(r[2]), "=r"(r[3]) : "r"(addr));
}
__device__ __forceinline__ void mma16816(float* c, const uint32_t* a,
                                         uint32_t b0, uint32_t b1) {
    asm volatile(
        "mma.sync.aligned.m16n8k16.row.col.f32.bf16.bf16.f32 "
        "{%0,%1,%2,%3}, {%4,%5,%6,%7}, {%8,%9}, {%0,%1,%2,%3};"
        : "+f"(c[0]), "+f"(c[1]), "+f"(c[2]), "+f"(c[3])
        : "r"(a[0]), "r"(a[1]), "r"(a[2]), "r"(a[3]), "r"(b0), "r"(b1));
}

// ---------------------------------------------------------------------------
// Pre-pass: E fp32 -> bf16 row-major
// ---------------------------------------------------------------------------
__global__ void convE_kernel(const float* __restrict__ E) {
    int i = blockIdx.x * blockDim.x + threadIdx.x;          // float2 pairs
    const float2 v = reinterpret_cast<const float2*>(E)[i];
    __nv_bfloat162 b;
    b.x = __float2bfloat16_rn(v.x);
    b.y = __float2bfloat16_rn(v.y);
    reinterpret_cast<__nv_bfloat162*>(g_Ebf)[i] = b;
}

// ---------------------------------------------------------------------------
// Pre-pass: transpose-convert x[b][d][p] -> g_Zbf[n][d] bf16  (n = b*1024+p)
// ---------------------------------------------------------------------------
__global__ void convZ_kernel(const float* __restrict__ x) {
    __shared__ float t[32][129];
    const int bz = blockIdx.x;
    const int b  = bz >> 7;
    const int r  = bz & 127;
    const int dc = r >> 3;
    const int pc = r & 7;
    const int tid = threadIdx.x;

    const float* xb = x + (size_t)b * (D_ * P_) + (size_t)(dc * 32) * P_ + pc * 128;
#pragma unroll
    for (int j = 0; j < 16; j++) {
        int e = tid + j * 256;
        int d = e >> 7, p = e & 127;
        t[d][p] = xb[(size_t)d * P_ + p];
    }
    __syncthreads();

    const int n0 = b * P_ + pc * 128;
#pragma unroll
    for (int j = 0; j < 8; j++) {
        int f = tid + j * 256;
        int nl = f >> 4, d2 = f & 15;
        __nv_bfloat162 v;
        v.x = __float2bfloat16_rn(t[d2 * 2][nl]);
        v.y = __float2bfloat16_rn(t[d2 * 2 + 1][nl]);
        reinterpret_cast<__nv_bfloat162*>(g_Zbf)[(size_t)(n0 + nl) * (D_ / 2) + dc * 16 + d2] = v;
    }
}

// ---------------------------------------------------------------------------
// enorm[k] = sum_d E[k][d]^2  (exact fp32 on originals)
// ---------------------------------------------------------------------------
__global__ void enorm_kernel(const float* __restrict__ E) {
    int k    = blockIdx.x * 8 + (threadIdx.x >> 5);
    int lane = threadIdx.x & 31;
    const float* row = E + (size_t)k * D_;
    float s = 0.f;
#pragma unroll
    for (int d = lane; d < D_; d += 32) {
        float v = row[d];
        s = fmaf(v, v, s);
    }
#pragma unroll
    for (int o = 16; o; o >>= 1) s += __shfl_xor_sync(0xffffffffu, s, o);
    if (lane == 0) g_enorm[k] = s;
}

// ---------------------------------------------------------------------------
// Main: bf16 mma.sync GEMM (A persistent in registers) + eps-window argmin +
// exact refinement + gather + transpose + loss.
// CTA = 128 rows, 8 warps (16 rows each), 64-code tiles, 3-stage cp.async ring.
// ---------------------------------------------------------------------------
__global__ __launch_bounds__(256, 1)
void vq_main(const float* __restrict__ x, const float* __restrict__ E,
             float* __restrict__ out)
{
    extern __shared__ unsigned char sm_raw[];
    const uint32_t smem_base = smem_u32(sm_raw);
    float* en_sm = reinterpret_cast<float*>(sm_raw + SM_EN);
    int*   kbest = reinterpret_cast<int*>(sm_raw + SM_KB);
    float* lred  = reinterpret_cast<float*>(sm_raw + SM_LRED);

    const int tid  = threadIdx.x;
    const int wid  = tid >> 5;
    const int lane = tid & 31;
    const int n0   = blockIdx.x * TM;
    const int b    = n0 >> 10;
    const int p0   = n0 & (P_ - 1);
    const float* xb = x + (size_t)b * (D_ * P_) + p0;   // xb[d*P_ + p]

    // exact enorm -> smem
#pragma unroll
    for (int j = 0; j < 16; j++) en_sm[tid + j * 256] = g_enorm[tid + j * 256];

    // ---- stage A (128 rows) into ring area, then ldmatrix into registers ----
#pragma unroll
    for (int i = 0; i < 32; i++) {
        int c = tid + i * 256;               // 0..8191
        int m = c >> 6, d8 = c & 63;
        cp_async16(smem_base + SM_RING + (uint32_t)(m * ASTRIDE + d8 * 16),
                   g_Zbf + ((size_t)(n0 + m) * D_ + d8 * 8));
    }
    cp_commit();
    cp_wait0();
    __syncthreads();

    uint32_t afr[32][4];                     // persistent A fragments (K=512)
    {
        const uint32_t aAddr = smem_base + SM_RING
            + (uint32_t)((wid * 16 + (lane & 15)) * ASTRIDE + (lane >> 4) * 16);
#pragma unroll
        for (int ks = 0; ks < 32; ks++) ldsm_x4(afr[ks], aAddr + ks * 32);
    }
    __syncthreads();                         // A regs loaded; ring reusable for B

    // ---- B pipeline prologue: tiles 0 and 1 ----
#pragma unroll
    for (int i = 0; i < 16; i++) {
        int c = tid + i * 256;               // 0..4095
        int kk = c >> 6, d8 = c & 63;
        cp_async16(smem_base + SM_RING + (uint32_t)(kk * ASTRIDE + d8 * 16),
                   g_Ebf + ((size_t)kk * D_ + d8 * 8));
    }
    cp_commit();
#pragma unroll
    for (int i = 0; i < 16; i++) {
        int c = tid + i * 256;
        int kk = c >> 6, d8 = c & 63;
        cp_async16(smem_base + SM_RING + (uint32_t)(SM_BSZ + kk * ASTRIDE + d8 * 16),
                   g_Ebf + ((size_t)(TK + kk) * D_ + d8 * 8));
    }
    cp_commit();

    // B ldmatrix lane addressing (validated in R9)
    const int bj   = lane >> 3;              // 0..3
    const int brow = ((bj >> 1) * 8) + (lane & 7);
    const int bkof = (bj & 1) * 16;
    const int tig  = lane & 3;

    // per-thread trackers: slot 0 -> row g, slot 1 -> row g+8
    float bestv[2] = {3.402823e38f, 3.402823e38f};
    int   besti[2] = {0, 0};
    float cv[2][4];
    int   ci[2][4];
#pragma unroll
    for (int s2 = 0; s2 < 2; s2++)
#pragma unroll
        for (int j = 0; j < 4; j++) { cv[s2][j] = 3.402823e38f; ci[s2][j] = 0; }

    int buf = 0;                             // ring cursor (t % 3)
    for (int t = 0; t < NKT; ++t) {
        cp_wait1();                          // tile t's group complete
        __syncthreads();                     // visible to all; prev consumers done

        const uint32_t bAddr = smem_base + SM_RING + (uint32_t)(buf * SM_BSZ)
                             + (uint32_t)(brow * ASTRIDE + bkof);

        float acc[8][4];
#pragma unroll
        for (int n = 0; n < 8; n++)
#pragma unroll
            for (int j = 0; j < 4; j++) acc[n][j] = 0.f;

#pragma unroll 2
        for (int ks = 0; ks < 32; ks++) {
            uint32_t bf0[4], bf1[4], bf2[4], bf3[4];
            ldsm_x4(bf0, bAddr + ks * 32);
            ldsm_x4(bf1, bAddr + 16u * ASTRIDE + ks * 32);
            ldsm_x4(bf2, bAddr + 32u * ASTRIDE + ks * 32);
            ldsm_x4(bf3, bAddr + 48u * ASTRIDE + ks * 32);
            mma16816(acc[0], afr[ks], bf0[0], bf0[1]);
            mma16816(acc[1], afr[ks], bf0[2], bf0[3]);
            mma16816(acc[2], afr[ks], bf1[0], bf1[1]);
            mma16816(acc[3], afr[ks], bf1[2], bf1[3]);
            mma16816(acc[4], afr[ks], bf2[0], bf2[1]);
            mma16816(acc[5], afr[ks], bf2[2], bf2[3]);
            mma16816(acc[6], afr[ks], bf3[0], bf3[1]);
            mma16816(acc[7], afr[ks], bf3[2], bf3[3]);
        }

        // prefetch tile t+2 into the buffer being vacated (safe: all warps past
        // tile t-1's reads by this point — they crossed this iteration's barrier)
        if (t + 2 < NKT) {
            const int k0n = (t + 2) * TK;
            const uint32_t dstb = smem_base + SM_RING
                + (uint32_t)(((buf + 2) % 3) * SM_BSZ);
#pragma unroll
            for (int i = 0; i < 16; i++) {
                int c = tid + i * 256;
                int kk = c >> 6, d8 = c & 63;
                cp_async16(dstb + (uint32_t)(kk * ASTRIDE + d8 * 16),
                           g_Ebf + ((size_t)(k0n + kk) * D_ + d8 * 8));
            }
        }
        cp_commit();

        // score + candidate tracking (approx scores, exact enorm)
        const int kt0 = t * TK;
#pragma unroll
        for (int n = 0; n < 8; n++) {
            const int kb = kt0 + n * 8 + tig * 2;
            const float2 en2 = *reinterpret_cast<const float2*>(&en_sm[kb]);
#pragma unroll
            for (int s2 = 0; s2 < 2; s2++) {
#pragma unroll
                for (int jj = 0; jj < 2; jj++) {
                    const int k = kb + jj;
                    float s = fmaf(-2.f, acc[n][s2 * 2 + jj],
                                   jj ? en2.y : en2.x);
                    if (s < bestv[s2] + EPS) {
                        int jm = 0; float vm = cv[s2][0];
#pragma unroll
                        for (int j = 1; j < 4; j++)
                            if (cv[s2][j] > vm) { vm = cv[s2][j]; jm = j; }
                        if (s < vm) { cv[s2][jm] = s; ci[s2][jm] = k; }
                        if (s < bestv[s2]) { bestv[s2] = s; besti[s2] = k; }
                    }
                }
            }
        }

        buf = (buf + 1) % 3;
    }

    // ---- finalize per row: quad merge + exact fp32 refinement ----
    const unsigned qmask = 0xFu << (lane & 28);
#pragma unroll
    for (int s2 = 0; s2 < 2; s2++) {
        const int m = wid * 16 + (lane >> 2) + s2 * 8;   // row in CTA
        float bv = bestv[s2];
        int   bi = besti[s2];
#pragma unroll
        for (int off = 1; off <= 2; off <<= 1) {
            float ov = __shfl_xor_sync(qmask, bv, off);
            int   oi = __shfl_xor_sync(qmask, bi, off);
            if (ov < bv || (ov == bv && oi < bi)) { bv = ov; bi = oi; }
        }
        int cnt = 0;
#pragma unroll
        for (int j = 0; j < 4; j++)
            if (cv[s2][j] <= bv + EPS) cnt++;
        cnt += __shfl_xor_sync(qmask, cnt, 1);
        cnt += __shfl_xor_sync(qmask, cnt, 2);

        int choice = bi;
        if (cnt > 1) {
            float es = 3.402823e38f;
            int   ek = 0x7fffffff;
#pragma unroll
            for (int j = 0; j < 4; j++) {
                if (cv[s2][j] <= bv + EPS) {
                    const int kk2 = ci[s2][j];
                    const float* Er = E + (size_t)kk2 * D_;
                    float dot = 0.f;
#pragma unroll 8
                    for (int d = 0; d < D_; d++)
                        dot = fmaf(xb[(size_t)d * P_ + m], Er[d], dot);
                    float se = fmaf(-2.f, dot, en_sm[kk2]);
                    if (se < es || (se == es && kk2 < ek)) { es = se; ek = kk2; }
                }
            }
#pragma unroll
            for (int off = 1; off <= 2; off <<= 1) {
                float ov = __shfl_xor_sync(qmask, es, off);
                int   oi = __shfl_xor_sync(qmask, ek, off);
                if (ov < es || (ov == es && oi < ek)) { es = ov; ek = oi; }
            }
            choice = ek;
        }
        if ((lane & 3) == 0) kbest[m] = choice;
    }
    __syncthreads();

    // ---- gather + transpose write + loss (elementwise fp32 originals) ----
    const int p      = tid & 127;
    const int dstart = tid >> 7;
    const int myk    = kbest[p];
    const float* Er  = E + (size_t)myk * D_;
    float* ob        = out + (size_t)b * (D_ * P_) + p0;
    float lsum = 0.f;
#pragma unroll 4
    for (int d = dstart; d < D_; d += 2) {
        float q = Er[d];
        float z = xb[(size_t)d * P_ + p];
        ob[(size_t)d * P_ + p] = q;
        float df = z - q;
        lsum = fmaf(df, df, lsum);
    }

    __syncthreads();
    lred[tid] = lsum;
    __syncthreads();
    for (int s = 128; s > 0; s >>= 1) {
        if (tid < s) lred[tid] += lred[tid + s];
        __syncthreads();
    }
    if (tid == 0) g_losspart[blockIdx.x] = lred[0];
}

// ---------------------------------------------------------------------------
// Final loss: loss = 1.25 * mean((z-q)^2)
// ---------------------------------------------------------------------------
__global__ void loss_kernel(float* __restrict__ out, int write_loss) {
    __shared__ float sh[NBLK];
    int tid = threadIdx.x;
    sh[tid] = g_losspart[tid];
    __syncthreads();
    for (int s = NBLK / 2; s > 0; s >>= 1) {
        if (tid < s) sh[tid] += sh[tid + s];
        __syncthreads();
    }
    if (tid == 0 && write_loss) {
        float m = sh[0] / (float)((size_t)N_ * D_);
        out[(size_t)N_ * D_] = m + 0.25f * m;
    }
}

extern "C" void kernel_launch(void* const* d_in, const int* in_sizes, int n_in,
                              void* d_out, int out_size) {
    const float* x = (const float*)d_in[0];
    const float* E = (const float*)d_in[1];
    if (n_in >= 2 && in_sizes[0] == K_ * D_ && in_sizes[1] == N_ * D_) {
        const float* t = x; x = E; E = t;   // defensive input-order swap
    }
    float* out = (float*)d_out;

    cudaFuncSetAttribute(vq_main, cudaFuncAttributeMaxDynamicSharedMemorySize, SM_TOTAL);

    convE_kernel<<<K_ * D_ / 2 / 256, 256>>>(E);
    convZ_kernel<<<4096, 256>>>(x);
    enorm_kernel<<<K_ / 8, 256>>>(E);
    vq_main<<<NBLK, 256, SM_TOTAL>>>(x, E, out);
    loss_kernel<<<1, NBLK>>>(out, out_size > N_ * D_ ? 1 : 0);
}